// round 1
// baseline (speedup 1.0000x reference)
#include <cuda_runtime.h>

// KAN layer forward:
//   out[b,o] = sum_i mask[s] * ( scale_base[s]*silu(x) + scale_sp[s]*sum_j coef[s,j]*B3_j(x) )
//   where s = o*64+i, x = inputs[b,i], B3 = cubic B-spline basis on the
//   extended grid (6 interior knots + 3 each side, 12 knots total, 11 -> 8 basis).
//
// One thread owns one edge s: knots, reciprocal denominators, and scaled coef
// live in registers; it loops over BITER batch rows. Reduction over i (64
// lanes, 2 warps) via shfl + 2-slot smem handoff, double-buffered so only one
// __syncthreads per iteration.

#define IN_DIM   64
#define OUT_DIM  64
#define NUMG     5
#define NCOEF    8
#define BY       4      // batch rows in flight per block
#define BITER    16     // batch rows per thread
#define THREADS  (IN_DIM * BY)

__global__ __launch_bounds__(THREADS, 2)
void kan_kernel(const float* __restrict__ inp,
                const float* __restrict__ gridp,
                const float* __restrict__ coefp,
                const float* __restrict__ sbase,
                const float* __restrict__ ssp,
                const float* __restrict__ maskp,
                float* __restrict__ out,
                int batch)
{
    const int i  = threadIdx.x;      // 0..63  (input index)
    const int ty = threadIdx.y;      // 0..BY-1
    const int o  = blockIdx.x;       // output index
    const int s  = o * IN_DIM + i;   // edge index

    // ---- per-edge setup (amortized over BITER batch rows) ----
    float t[12];
    {
        float g[6];
        #pragma unroll
        for (int j = 0; j < 6; ++j) g[j] = gridp[s * 6 + j];
        const float h = (g[5] - g[0]) * (1.0f / (float)NUMG);
        t[0] = g[0] - 3.0f * h;
        t[1] = g[0] - 2.0f * h;
        t[2] = g[0] - h;
        #pragma unroll
        for (int j = 0; j < 6; ++j) t[3 + j] = g[j];
        t[9]  = g[5] + h;
        t[10] = g[5] + 2.0f * h;
        t[11] = g[5] + 3.0f * h;
    }

    // reciprocal denominators (x-independent) — keeps all division/MUFU out of
    // the batch loop.
    float inv1[11], inv2[10], inv3[9];
    #pragma unroll
    for (int m = 0; m < 11; ++m) inv1[m] = 1.0f / (t[m + 1] - t[m]);
    #pragma unroll
    for (int m = 0; m < 10; ++m) inv2[m] = 1.0f / (t[m + 2] - t[m]);
    #pragma unroll
    for (int m = 0; m < 9;  ++m) inv3[m] = 1.0f / (t[m + 3] - t[m]);

    const float mk = maskp[s];
    const float a  = mk * sbase[s];   // folded silu scale
    const float w  = mk * ssp[s];     // folded spline scale
    float c[NCOEF];
    #pragma unroll
    for (int j = 0; j < NCOEF; ++j) c[j] = w * coefp[s * NCOEF + j];

    __shared__ float red[2][BY][2];   // double-buffered cross-warp partials

    const int b0 = blockIdx.y * (BY * BITER);

    #pragma unroll 1
    for (int it = 0; it < BITER; ++it) {
        const int b = b0 + it * BY + ty;
        float val = 0.0f;

        if (b < batch) {
            const float x = inp[b * IN_DIM + i];

            // degree-0 indicators on the 11 extended intervals
            float B[11];
            #pragma unroll
            for (int m = 0; m < 11; ++m)
                B[m] = (x >= t[m] && x < t[m + 1]) ? 1.0f : 0.0f;

            // Cox–de Boor: p = 1, 2, 3
            #pragma unroll
            for (int m = 0; m < 10; ++m)
                B[m] = (x - t[m]) * inv1[m] * B[m]
                     + (t[m + 2] - x) * inv1[m + 1] * B[m + 1];
            #pragma unroll
            for (int m = 0; m < 9; ++m)
                B[m] = (x - t[m]) * inv2[m] * B[m]
                     + (t[m + 3] - x) * inv2[m + 1] * B[m + 1];
            #pragma unroll
            for (int m = 0; m < 8; ++m)
                B[m] = (x - t[m]) * inv3[m] * B[m]
                     + (t[m + 4] - x) * inv3[m + 1] * B[m + 1];

            float y = 0.0f;
            #pragma unroll
            for (int j = 0; j < NCOEF; ++j) y = fmaf(c[j], B[j], y);

            const float sil = x * (1.0f / (1.0f + __expf(-x)));
            val = fmaf(a, sil, y);
        }

        // reduce over i: 32-lane shuffle, then combine the block's two warps
        // per ty-row through smem.
        #pragma unroll
        for (int off = 16; off > 0; off >>= 1)
            val += __shfl_xor_sync(0xffffffffu, val, off);

        const int buf = it & 1;
        if ((i & 31) == 0) red[buf][ty][i >> 5] = val;
        __syncthreads();
        if (i == 0 && b < batch)
            out[b * OUT_DIM + o] = red[buf][ty][0] + red[buf][ty][1];
        // no second barrier: next iteration writes the other buffer, and the
        // one-after-next write is ordered behind the next iteration's barrier.
    }
}

extern "C" void kernel_launch(void* const* d_in, const int* in_sizes, int n_in,
                              void* d_out, int out_size)
{
    const float* inp   = (const float*)d_in[0];   // (batch, 64)
    const float* gridp = (const float*)d_in[1];   // (4096, 6)
    const float* coefp = (const float*)d_in[2];   // (4096, 8)
    const float* sbase = (const float*)d_in[3];   // (4096,)
    const float* ssp   = (const float*)d_in[4];   // (4096,)
    const float* maskp = (const float*)d_in[5];   // (4096,)
    float* out = (float*)d_out;                   // (batch, 64)

    const int batch = in_sizes[0] / IN_DIM;

    const int chunk = BY * BITER;
    dim3 grid(OUT_DIM, (batch + chunk - 1) / chunk);
    dim3 block(IN_DIM, BY);
    kan_kernel<<<grid, block>>>(inp, gridp, coefp, sbase, ssp, maskp, out, batch);
}

// round 2
// speedup vs baseline: 3.8194x; 3.8194x over previous
#include <cuda_runtime.h>

// KAN layer forward, sparse uniform cubic B-spline formulation.
//
//   out[b,o] = sum_i mask[s]*( scale_base[s]*silu(x) + scale_sp[s]*spline_s(x) ),
//   s = o*64+i, x = inputs[b,i].
//
// The knot vector per edge is uniform (interior grid is linspace, extension
// uses the same h), so for cubic degree only 4 basis functions are nonzero at
// any x, with closed-form weights in u=(x-t_m)/h. Coefficients are staged in
// shared memory zero-padded by 3 on each side, so the dynamic 4-coef window
// c[m..m+3] never branches. One warp owns one (b,o): each lane evaluates
// edges i=lane and i=lane+32, then a pure shuffle reduction — no smem or
// barriers in the hot loop.

#define IN_DIM   64
#define OUT_DIM  64
#define NW       8      // warps per block
#define BITER    8      // batch rows per warp
#define THREADS  (NW * 32)
#define CPAD     17     // smem row stride (odd -> conflict-free across lanes)

__global__ __launch_bounds__(THREADS, 4)
void kan_kernel(const float* __restrict__ inp,
                const float* __restrict__ gridp,
                const float* __restrict__ coefp,
                const float* __restrict__ sbase,
                const float* __restrict__ ssp,
                const float* __restrict__ maskp,
                float* __restrict__ out,
                int batch)
{
    const int lane = threadIdx.x & 31;
    const int wrp  = threadIdx.x >> 5;      // 0..NW-1
    const int o    = blockIdx.x;            // output index

    // padded, pre-scaled coefficients: cpad[i][3+j] = mask*scale_sp*coef[s][j],
    // zeros at [0..2] and [11..13]; slots 14..16 are padding only.
    __shared__ float cpad[IN_DIM][CPAD];

    for (int idx = threadIdx.x; idx < IN_DIM * 14; idx += THREADS) {
        const int i  = idx / 14;
        const int jj = idx - i * 14;
        const int s  = o * IN_DIM + i;
        const int j  = jj - 3;
        float v = 0.0f;
        if (j >= 0 && j < 8)
            v = maskp[s] * ssp[s] * coefp[s * 8 + j];
        cpad[i][jj] = v;
    }

    // per-thread edge params for its two edges i = lane, lane+32
    float t0[2], invh[2], aa[2];
    #pragma unroll
    for (int e = 0; e < 2; ++e) {
        const int i = lane + 32 * e;
        const int s = o * IN_DIM + i;
        const float g0 = gridp[s * 6 + 0];
        const float g5 = gridp[s * 6 + 5];
        const float h  = (g5 - g0) * 0.2f;      // / NUM
        t0[e]   = g0 - 3.0f * h;                // leftmost extended knot
        invh[e] = 1.0f / h;
        aa[e]   = maskp[s] * sbase[s];          // folded silu scale
    }
    __syncthreads();

    const int b0 = blockIdx.y * (NW * BITER) + wrp;

    #pragma unroll 1
    for (int it = 0; it < BITER; ++it) {
        const int b = b0 + it * NW;
        float val = 0.0f;

        if (b < batch) {
            #pragma unroll
            for (int e = 0; e < 2; ++e) {
                const int i = lane + 32 * e;
                const float x  = inp[b * IN_DIM + i];

                // interval index on the 11 extended intervals
                const float mf = (x - t0[e]) * invh[e];
                int   mi = (int)floorf(mf);
                const float ok = (mi >= 0 && mi < 11) ? 1.0f : 0.0f;
                mi = max(0, min(10, mi));

                // uniform cubic B-spline weights at local coordinate u
                const float u  = mf - (float)mi;
                const float v  = 1.0f - u;
                const float u2 = u * u;
                const float u3 = u2 * u;
                const float w0 = v * v * v * (1.0f / 6.0f);
                const float w3 = u3 * (1.0f / 6.0f);
                const float w1 = (2.0f / 3.0f) - u2 + 0.5f * u3;
                const float w2 = 1.0f - w0 - w1 - w3;

                // nonzero coef window: basis j = mi-3+r  ->  padded idx mi+r
                const float* cr = &cpad[i][mi];
                float spl;
                spl = cr[0] * w0;
                spl = fmaf(cr[1], w1, spl);
                spl = fmaf(cr[2], w2, spl);
                spl = fmaf(cr[3], w3, spl);

                const float sil = __fdividef(x, 1.0f + __expf(-x));
                val += fmaf(aa[e], sil, ok * spl);
            }
        }

        // reduce the 64 edge contributions (2 per lane) across the warp
        #pragma unroll
        for (int off = 16; off > 0; off >>= 1)
            val += __shfl_xor_sync(0xffffffffu, val, off);

        if (lane == 0 && b < batch)
            out[b * OUT_DIM + o] = val;
    }
}

extern "C" void kernel_launch(void* const* d_in, const int* in_sizes, int n_in,
                              void* d_out, int out_size)
{
    const float* inp   = (const float*)d_in[0];   // (batch, 64)
    const float* gridp = (const float*)d_in[1];   // (4096, 6)
    const float* coefp = (const float*)d_in[2];   // (4096, 8)
    const float* sbase = (const float*)d_in[3];   // (4096,)
    const float* ssp   = (const float*)d_in[4];   // (4096,)
    const float* maskp = (const float*)d_in[5];   // (4096,)
    float* out = (float*)d_out;                   // (batch, 64)

    const int batch = in_sizes[0] / IN_DIM;
    const int chunk = NW * BITER;                 // rows per block
    dim3 grid(OUT_DIM, (batch + chunk - 1) / chunk);
    kan_kernel<<<grid, THREADS>>>(inp, gridp, coefp, sbase, ssp, maskp, out, batch);
}